// round 13
// baseline (speedup 1.0000x reference)
#include <cuda_runtime.h>
#include <cuda_bf16.h>
#include <cstdint>

#define B_ 512
#define D_ 256
#define P_ 196
#define N2 1024   // 2*B
#define P0 6      // positions beyond this: softmax chain converged to uniform

// exp(dot / T) with T=0.5 -> exp2(dot * 2*log2(e))
#define EXP_SCALE 2.8853900817779268f
#define LOG2E     1.4426950408889634f
#define LN2F      0.6931471805599453f
#define E_SQ      7.3890560989306495f   // e^2 = exp(u.u / T)

#define NTILE_FULL 36                   // 8x8 upper triangle
#define NTILE_AA   10                   // 4x4 upper triangle
#define GRID_MAIN  (P0 * NTILE_FULL + (P_ - P0) * NTILE_AA)   // 2116
// tiles for p < 128 (matches buildA chunk pg 0..3)
#define F_SPLIT    (P0 * NTILE_FULL + (128 - P0) * NTILE_AA)  // 1436

// ---------------- device scratch (no allocations allowed) ----------------
__device__ __nv_bfloat16 g_Zh[(size_t)P_ * N2 * D_];  // [p][row][d] bf16
__device__ float g_S[P_ * N2];      // per-row sums of exp(sim) (atomic accum)
__device__ float g_rn2[P_ * N2];    // per-row |z|^2 (diag correction)
__device__ float g_invA[P_ * B_];   // per-A-row 1/(||softmax||+1e-8)
__device__ float g_wtp[128 * P_];   // attention-sum partials (128 row-groups)
__device__ float g_dsum[P_];        // positive-pair dots (atomic accum, p<P0)

// ---------------- small helpers ----------------
__device__ __forceinline__ float ex2f(float x) {
    float y; asm("ex2.approx.f32 %0, %1;" : "=f"(y) : "f"(x)); return y;
}
__device__ __forceinline__ float lg2f(float x) {
    float y; asm("lg2.approx.f32 %0, %1;" : "=f"(y) : "f"(x)); return y;
}
__device__ __forceinline__ unsigned s2u(const void* p) {
    return (unsigned)__cvta_generic_to_shared(p);
}
__device__ __forceinline__ float warpSum(float v) {
    #pragma unroll
    for (int o = 16; o > 0; o >>= 1) v += __shfl_xor_sync(0xffffffffu, v, o);
    return v;
}
__device__ __forceinline__ float blockSum256(float v, float* sh) {
    int w = threadIdx.x >> 5, l = threadIdx.x & 31;
    v = warpSum(v);
    __syncthreads();
    if (l == 0) sh[w] = v;
    __syncthreads();
    if (w == 0) {
        float x = (l < 8) ? sh[l] : 0.0f;
        x = warpSum(x);
        if (l == 0) sh[0] = x;
    }
    __syncthreads();
    return sh[0];
}

#define CPA16(dst_, src_) \
    asm volatile("cp.async.cg.shared.global [%0], [%1], 16;" :: "r"(dst_), "l"(src_))
#define CPA_COMMIT() asm volatile("cp.async.commit_group;" ::: "memory")
#define CPA_WAITG1() asm volatile("cp.async.wait_group 1;"  ::: "memory")

#define LDSM4(r0_, r1_, r2_, r3_, addr_) \
    asm volatile("ldmatrix.sync.aligned.m8n8.x4.shared.b16 {%0,%1,%2,%3}, [%4];" \
        : "=r"(r0_), "=r"(r1_), "=r"(r2_), "=r"(r3_) : "r"(addr_))

#define MMA16816(c_, a_, b0_, b1_) \
    asm volatile("mma.sync.aligned.m16n8k16.row.col.f32.bf16.bf16.f32 " \
        "{%0,%1,%2,%3}, {%4,%5,%6,%7}, {%8,%9}, {%0,%1,%2,%3};" \
        : "+f"((c_)[0]), "+f"((c_)[1]), "+f"((c_)[2]), "+f"((c_)[3]) \
        : "r"((a_)[0]), "r"((a_)[1]), "r"((a_)[2]), "r"((a_)[3]), "r"(b0_), "r"(b1_))

// ---------------- zero accumulators (+ output) ----------------
__global__ __launch_bounds__(1024) void k_zero(float* out, int n) {
    int b = blockIdx.x, t = threadIdx.x;
    g_S[b * 1024 + t] = 0.0f;
    if (t == 0 && b < P_) g_dsum[b] = 0.0f;
    if (b == 0) for (int i = t; i < n; i += 1024) out[i] = 0.0f;
}

// ---------------- stage 1: global-feature softmax chain (p < P0 only) -------
__global__ __launch_bounds__(32) void k_buildG(const float* __restrict__ gf) {
    int b = blockIdx.x;
    int lane = threadIdx.x;
    float v[8];
    #pragma unroll
    for (int j = 0; j < 8; j++) v[j] = gf[b * D_ + j * 32 + lane];
    for (int p = 0; p < P0; p++) {
        float e[8], s = 0.0f, s2 = 0.0f;
        #pragma unroll
        for (int j = 0; j < 8; j++) {
            e[j] = ex2f(v[j] * LOG2E);
            s  += e[j];
            s2 += e[j] * e[j];
        }
        #pragma unroll
        for (int o = 16; o > 0; o >>= 1) {
            s  += __shfl_xor_sync(~0u, s,  o);
            s2 += __shfl_xor_sync(~0u, s2, o);
        }
        float inv_s = 1.0f / s;
        float q = s2 * inv_s * inv_s;
        float inv = 1.0f / (sqrtf(q) + 1e-8f);
        float sc = inv_s * inv;
        #pragma unroll
        for (int j = 0; j < 8; j++) {
            g_Zh[((size_t)p * N2 + B_ + b) * D_ + j * 32 + lane] =
                __float2bfloat16(e[j] * sc);
            v[j] = e[j] * inv_s;
        }
        if (lane == 0) g_rn2[p * N2 + B_ + b] = q * inv * inv;
    }
}

// ---------------- stage 2: local-feature softmax (32 p per block) ------------
// fp32 tile transposed [d][p], pitch 36 words; bf16 staging pitch 132 words.
// pg_base selects the p-chunk (pipelined with k_main).
#define TP 36
__global__ __launch_bounds__(256) void k_buildA(const float* __restrict__ outp, int pg_base) {
    __shared__ float tile[D_ * TP];          // 36864 B
    int pg = blockIdx.x + pg_base, b = blockIdx.y;
    int tid = threadIdx.x;
    // vector load phase: 8 x (LDG.128 -> STS.128)
    #pragma unroll
    for (int i = 0; i < 8; i++) {
        int idx = tid + (i << 8);            // 0..2047
        int d = idx >> 3, p4 = idx & 7;
        int pbase = pg * 32 + p4 * 4;
        if (pbase > P_ - 4) pbase = P_ - 4;  // clamp: dup columns land in discarded p>=196 slots
        float4 v = *(const float4*)(outp + ((size_t)b * D_ + d) * P_ + pbase);
        *(float4*)(tile + d * TP + p4 * 4) = v;
    }
    __syncthreads();
    int dg = tid & 7, pl = tid >> 3;
    int p  = pg * 32 + pl;
    float x[32];
    #pragma unroll
    for (int j = 0; j < 32; j++) x[j] = tile[(dg + 8 * j) * TP + pl];
    float e[32], s = 0.0f, s2 = 0.0f;
    #pragma unroll
    for (int j = 0; j < 32; j++) {
        e[j] = ex2f(x[j] * LOG2E);
        s += e[j]; s2 += e[j] * e[j];
    }
    s  += __shfl_xor_sync(~0u, s, 1);  s  += __shfl_xor_sync(~0u, s, 2);  s  += __shfl_xor_sync(~0u, s, 4);
    s2 += __shfl_xor_sync(~0u, s2, 1); s2 += __shfl_xor_sync(~0u, s2, 2); s2 += __shfl_xor_sync(~0u, s2, 4);
    float inv_s = 1.0f / s;
    float q = s2 * inv_s * inv_s;
    float inv = 1.0f / (sqrtf(q) + 1e-8f);
    float sc = inv_s * inv;
    if (dg == 0 && p < P_) {
        g_rn2[p * N2 + b] = q * inv * inv;
        g_invA[p * B_ + b] = inv;
    }
    __syncthreads();
    __nv_bfloat16* stg = (__nv_bfloat16*)tile;   // reuse: 32 rows x 264 bf16 (132 words)
    #pragma unroll
    for (int j = 0; j < 32; j++) stg[pl * 264 + dg + 8 * j] = __float2bfloat16(e[j] * sc);
    __syncthreads();
    const uint4* stg4 = (const uint4*)tile;      // row pitch 132 words = 33 uint4
    uint4* dst = (uint4*)g_Zh;                   // row = 128 u32 = 32 uint4
    #pragma unroll
    for (int i = 0; i < 4; i++) {
        int idx = tid + (i << 8);                // 0..1023
        int pl2 = idx >> 5, dw = idx & 31;
        int pp = pg * 32 + pl2;
        if (pp < P_) dst[((size_t)pp * N2 + b) * 32 + dw] = stg4[pl2 * 33 + dw];
    }
}

// ---------------- attention weights: 128 coalesced partial blocks ------------
__global__ __launch_bounds__(256) void k_wt(const float* __restrict__ att) {
    int t = threadIdx.x;
    int g = blockIdx.x;               // 128 blocks, 32 rows each
    if (t >= P_) return;
    const float* base = att + (size_t)(g * 32) * P_ + t;
    float s = 0.0f;
    #pragma unroll 8
    for (int r = 0; r < 32; r++) s += base[(size_t)r * P_];
    g_wtp[g * P_ + t] = s;
}

// ---------------- main: one 128x128 tile pair per CTA, packed grid ----------
#define CH_STRIDE 80                 // 32 bf16 = 64B + 16 pad per row
#define CH_BYTES  (128 * CH_STRIDE)  // one operand chunk: 10240
#define STG_BYTES (2 * CH_BYTES)     // A chunk + B chunk per stage
#define NSTAGE    3
#define SM_DYN    (NSTAGE * STG_BYTES)   // 61440

__global__ __launch_bounds__(256, 2) void k_main_mma(int f_base) {
    extern __shared__ __align__(1024) char dynsm[];
    __shared__ float redsm[4 * 128];
    __shared__ float colsm[2][128];
    __shared__ float shred[32];

    uint32_t sm_u = s2u(dynsm);

    int tid  = threadIdx.x;
    int wid  = tid >> 5;
    int lane = tid & 31;
    int gq   = lane >> 2;
    int t4   = lane & 3;

    // flat packed decode: P0 p's x 36 tiles, then (P_-P0) p's x 10 tiles
    int f = blockIdx.x + f_base;
    int p, ti, width;
    if (f < P0 * NTILE_FULL) {
        p = f / NTILE_FULL; ti = f - p * NTILE_FULL; width = 8;
    } else {
        int f2 = f - P0 * NTILE_FULL;
        int pr = f2 / NTILE_AA;
        p = P0 + pr; ti = f2 - pr * NTILE_AA; width = 4;
    }
    int rt = 0;
    while (ti >= width - rt) { ti -= width - rt; rt++; }
    int ct = rt + ti;
    int r0 = rt << 7, c0 = ct << 7;
    bool diag = (rt == ct);

    int mwarp = wid & 1, nwarp = wid >> 1;
    int mbase = mwarp << 6;
    int nwbase = nwarp << 5;

    const __nv_bfloat16* Zh = g_Zh + (size_t)p * (N2 * D_);

    int q    = lane >> 3;
    int arow = ((q & 1) << 3) + (lane & 7);
    uint32_t aoff = (uint32_t)(arow * CH_STRIDE + ((q >> 1) << 4));
    uint32_t boff = (uint32_t)(((((q >> 1) << 3) + (lane & 7)) * CH_STRIDE) + ((q & 1) << 4));

    // per-thread cp.async coords (2 granules per operand per chunk)
    int n_0 = tid >> 2,         g4_0 = tid & 3;
    int n_1 = (tid + 256) >> 2, g4_1 = (tid + 256) & 3;

    // ---- prologue: stages 0,1 ----
    #pragma unroll
    for (int st = 0; st < 2; st++) {
        uint32_t sbase = sm_u + st * STG_BYTES;
        int kc = st;
        CPA16(sbase + (uint32_t)(n_0 * CH_STRIDE + g4_0 * 16),
              Zh + (size_t)(r0 + n_0) * D_ + kc * 32 + g4_0 * 8);
        CPA16(sbase + (uint32_t)(n_1 * CH_STRIDE + g4_1 * 16),
              Zh + (size_t)(r0 + n_1) * D_ + kc * 32 + g4_1 * 8);
        if (!diag) {
            CPA16(sbase + (uint32_t)(CH_BYTES + n_0 * CH_STRIDE + g4_0 * 16),
                  Zh + (size_t)(c0 + n_0) * D_ + kc * 32 + g4_0 * 8);
            CPA16(sbase + (uint32_t)(CH_BYTES + n_1 * CH_STRIDE + g4_1 * 16),
                  Zh + (size_t)(c0 + n_1) * D_ + kc * 32 + g4_1 * 8);
        }
        CPA_COMMIT();
    }

    float acc[4][4][4];
    #pragma unroll
    for (int mb = 0; mb < 4; mb++)
        #pragma unroll
        for (int nb = 0; nb < 4; nb++)
            #pragma unroll
            for (int r = 0; r < 4; r++) acc[mb][nb][r] = 0.0f;

    uint32_t bsel = diag ? 0u : (uint32_t)CH_BYTES;   // diag reuses A chunk as B

    int stage = 0;
    #pragma unroll 1
    for (int kc = 0; kc < 8; kc++) {
        CPA_WAITG1();
        __syncthreads();
        // prefetch kc+2
        int kn = kc + 2;
        if (kn < 8) {
            int sn = kn % NSTAGE;
            uint32_t sbase = sm_u + sn * STG_BYTES;
            CPA16(sbase + (uint32_t)(n_0 * CH_STRIDE + g4_0 * 16),
                  Zh + (size_t)(r0 + n_0) * D_ + kn * 32 + g4_0 * 8);
            CPA16(sbase + (uint32_t)(n_1 * CH_STRIDE + g4_1 * 16),
                  Zh + (size_t)(r0 + n_1) * D_ + kn * 32 + g4_1 * 8);
            if (!diag) {
                CPA16(sbase + (uint32_t)(CH_BYTES + n_0 * CH_STRIDE + g4_0 * 16),
                      Zh + (size_t)(c0 + n_0) * D_ + kn * 32 + g4_0 * 8);
                CPA16(sbase + (uint32_t)(CH_BYTES + n_1 * CH_STRIDE + g4_1 * 16),
                      Zh + (size_t)(c0 + n_1) * D_ + kn * 32 + g4_1 * 8);
            }
        }
        CPA_COMMIT();

        uint32_t abase = sm_u + (uint32_t)(stage * STG_BYTES);
        uint32_t bbase = abase + bsel;
        #pragma unroll
        for (int kh = 0; kh < 2; kh++) {
            uint32_t a[4][4];
            #pragma unroll
            for (int mb = 0; mb < 4; mb++) {
                uint32_t addr = abase + (uint32_t)((mbase + (mb << 4)) * CH_STRIDE + (kh << 5)) + aoff;
                LDSM4(a[mb][0], a[mb][1], a[mb][2], a[mb][3], addr);
            }
            uint32_t bf[2][4];
            #pragma unroll
            for (int n2 = 0; n2 < 2; n2++) {
                uint32_t addr = bbase + (uint32_t)((nwbase + (n2 << 4)) * CH_STRIDE + (kh << 5)) + boff;
                LDSM4(bf[n2][0], bf[n2][1], bf[n2][2], bf[n2][3], addr);
            }
            #pragma unroll
            for (int mb = 0; mb < 4; mb++) {
                MMA16816(acc[mb][0], a[mb], bf[0][0], bf[0][1]);
                MMA16816(acc[mb][1], a[mb], bf[0][2], bf[0][3]);
                MMA16816(acc[mb][2], a[mb], bf[1][0], bf[1][1]);
                MMA16816(acc[mb][3], a[mb], bf[1][2], bf[1][3]);
            }
        }
        stage++; if (stage == NSTAGE) stage = 0;
    }

    // ---- epilogue: exp, rowsums (+ colsums if off-diag), pair dots ----
    bool isdiag4 = (p < P0) && (ct == rt + 4);
    float cs[8];
    #pragma unroll
    for (int i = 0; i < 8; i++) cs[i] = 0.0f;
    float dpart = 0.0f;
    float rs_reg[8];
    #pragma unroll
    for (int mb = 0; mb < 4; mb++) {
        int row0 = mbase + (mb << 4) + gq;
        float rs0 = 0.0f, rs1 = 0.0f;
        #pragma unroll
        for (int nb = 0; nb < 4; nb++) {
            int col = nwbase + (nb << 3) + (t4 << 1);
            float* c = acc[mb][nb];
            float e0 = ex2f(c[0] * EXP_SCALE);
            float e1 = ex2f(c[1] * EXP_SCALE);
            float e2 = ex2f(c[2] * EXP_SCALE);
            float e3 = ex2f(c[3] * EXP_SCALE);
            rs0 += e0 + e1;
            rs1 += e2 + e3;
            cs[nb * 2 + 0] += e0 + e2;
            cs[nb * 2 + 1] += e1 + e3;
            if (isdiag4) {
                if (col == row0)          dpart += c[0];
                else if (col + 1 == row0) dpart += c[1];
                if (col == row0 + 8)          dpart += c[2];
                else if (col + 1 == row0 + 8) dpart += c[3];
            }
        }
        rs_reg[mb * 2 + 0] = rs0;
        rs_reg[mb * 2 + 1] = rs1;
    }

    // rowsums: reduce over t4, combine across nwarp via smem, one atomic per row
    #pragma unroll
    for (int i = 0; i < 8; i++) {
        rs_reg[i] += __shfl_xor_sync(~0u, rs_reg[i], 1);
        rs_reg[i] += __shfl_xor_sync(~0u, rs_reg[i], 2);
    }
    if (t4 == 0) {
        #pragma unroll
        for (int mb = 0; mb < 4; mb++) {
            int row0 = mbase + (mb << 4) + gq;
            redsm[nwarp * 128 + row0]     = rs_reg[mb * 2 + 0];
            redsm[nwarp * 128 + row0 + 8] = rs_reg[mb * 2 + 1];
        }
    }
    // colsums: reduce across gq lanes, combine across mwarp via smem
    if (!diag) {
        #pragma unroll
        for (int i = 0; i < 8; i++) {
            cs[i] += __shfl_xor_sync(~0u, cs[i], 4);
            cs[i] += __shfl_xor_sync(~0u, cs[i], 8);
            cs[i] += __shfl_xor_sync(~0u, cs[i], 16);
        }
        if (lane < 4) {
            #pragma unroll
            for (int i = 0; i < 8; i++)
                colsm[mwarp][nwbase + ((i >> 1) << 3) + lane * 2 + (i & 1)] = cs[i];
        }
    }
    __syncthreads();
    if (tid < 128) {
        float rsum = redsm[tid] + redsm[128 + tid] + redsm[256 + tid] + redsm[384 + tid];
        atomicAdd(&g_S[p * N2 + r0 + tid], rsum);
        if (!diag)
            atomicAdd(&g_S[p * N2 + c0 + tid], colsm[0][tid] + colsm[1][tid]);
    }
    if (isdiag4) {
        float dp = blockSum256(dpart, shred);
        if (tid == 0) atomicAdd(&g_dsum[p], dp);
    }
}

// ---------------- per-position loss -> atomic into out[0] ----------------
__global__ __launch_bounds__(256) void k_final(float* out) {
    int p = blockIdx.x;
    __shared__ float sh[32];
    __shared__ float sh_wt;
    // parallel attention-weight partial reduction (128 partials)
    float wt_part = (threadIdx.x < 128) ? g_wtp[threadIdx.x * P_ + p] : 0.0f;
    float wt = blockSum256(wt_part, sh);
    if (threadIdx.x == 0) sh_wt = wt;

    if (p < P0) {
        float acc = 0.0f;
        for (int r = threadIdx.x; r < N2; r += 256) {
            float self = ex2f(g_rn2[p * N2 + r] * EXP_SCALE);
            acc += lg2f(g_S[p * N2 + r] - self);
        }
        acc = blockSum256(acc, sh) * LN2F;
        if (threadIdx.x == 0) {
            atomicAdd(out, (acc - 4.0f * g_dsum[p]) * sh_wt *
                           (1.0f / ((float)N2 * (float)B_ * (float)P_)));
        }
    } else {
        // converged regime: G rows all equal u (entries 1/16).
        float accL = 0.0f, accT = 0.0f, accD = 0.0f;
        for (int r = threadIdx.x; r < B_; r += 256) {
            float Saa  = g_S[p * N2 + r];                   // AA exp-rowsum (incl. bf16 self)
            float inv  = g_invA[p * B_ + r];
            float dAu  = inv * 0.0625f;                     // dot(A_r, u)
            float E    = ex2f(dAu * EXP_SCALE);             // exp(2*dAu)
            float self = ex2f(g_rn2[p * N2 + r] * EXP_SCALE);
            accL += lg2f(Saa + 512.0f * E - self);
            accT += E;
            accD += dAu;
        }
        accL = blockSum256(accL, sh);
        accT = blockSum256(accT, sh);
        accD = blockSum256(accD, sh);
        if (threadIdx.x == 0) {
            // G rows: S = T_A + 512*e^2, self = e^2 -> 512 identical log terms
            float logAll = (accL + 512.0f * lg2f(accT + 511.0f * E_SQ)) * LN2F;
            atomicAdd(out, (logAll - 4.0f * accD) * sh_wt *
                           (1.0f / ((float)N2 * (float)B_ * (float)P_)));
        }
    }
}

// ---------------- launch ----------------
extern "C" void kernel_launch(void* const* d_in, const int* in_sizes, int n_in,
                              void* d_out, int out_size) {
    const float* gf = nullptr; const float* att = nullptr; const float* outp = nullptr;
    for (int i = 0; i < n_in; i++) {
        if (in_sizes[i] == B_ * D_)            gf   = (const float*)d_in[i];
        else if (in_sizes[i] == B_ * 8 * P_)   att  = (const float*)d_in[i];
        else if (in_sizes[i] == B_ * D_ * P_)  outp = (const float*)d_in[i];
    }
    if (!gf)   gf   = (const float*)d_in[0];
    if (!att)  att  = (const float*)d_in[1];
    if (!outp) outp = (const float*)d_in[2];

    cudaFuncSetAttribute(k_main_mma, cudaFuncAttributeMaxDynamicSharedMemorySize, SM_DYN);

    // one-time resources (no device memory involved); work per call is identical
    static cudaStream_t s_g = nullptr, s_z = nullptr, s_a = nullptr;
    static cudaEvent_t ev_root = nullptr, ev_g = nullptr, ev_z = nullptr,
                       ev_w = nullptr, ev_a1 = nullptr, ev_a2 = nullptr;
    if (s_g == nullptr) {
        cudaStreamCreateWithFlags(&s_g, cudaStreamNonBlocking);
        cudaStreamCreateWithFlags(&s_z, cudaStreamNonBlocking);
        cudaStreamCreateWithFlags(&s_a, cudaStreamNonBlocking);
        cudaEventCreateWithFlags(&ev_root, cudaEventDisableTiming);
        cudaEventCreateWithFlags(&ev_g,    cudaEventDisableTiming);
        cudaEventCreateWithFlags(&ev_z,    cudaEventDisableTiming);
        cudaEventCreateWithFlags(&ev_w,    cudaEventDisableTiming);
        cudaEventCreateWithFlags(&ev_a1,   cudaEventDisableTiming);
        cudaEventCreateWithFlags(&ev_a2,   cudaEventDisableTiming);
    }

    // fork from the (captured) default stream
    cudaEventRecord(ev_root, 0);
    cudaStreamWaitEvent(s_g, ev_root, 0);
    cudaStreamWaitEvent(s_z, ev_root, 0);
    cudaStreamWaitEvent(s_a, ev_root, 0);

    k_buildG<<<B_, 32, 0, s_g>>>(gf);
    cudaEventRecord(ev_g, s_g);

    k_zero<<<P_, 1024, 0, s_z>>>((float*)d_out, out_size);
    cudaEventRecord(ev_z, s_z);
    k_wt<<<128, 256, 0, s_z>>>(att);
    cudaEventRecord(ev_w, s_z);

    // buildA chunk 1 (p 0..127) on default stream
    k_buildA<<<dim3(4, B_), 256>>>(outp, 0);
    cudaEventRecord(ev_a1, 0);

    // buildA chunk 2 (p 128..195) on side stream, sequenced after chunk 1
    cudaStreamWaitEvent(s_a, ev_a1, 0);
    k_buildA<<<dim3(3, B_), 256, 0, s_a>>>(outp, 4);
    cudaEventRecord(ev_a2, s_a);

    // k_main chunk 1 (tiles for p<128) overlaps buildA chunk 2
    cudaStreamWaitEvent(0, ev_g, 0);
    cudaStreamWaitEvent(0, ev_z, 0);
    k_main_mma<<<F_SPLIT, 256, SM_DYN>>>(0);

    // k_main chunk 2 needs buildA chunk 2
    cudaStreamWaitEvent(0, ev_a2, 0);
    k_main_mma<<<GRID_MAIN - F_SPLIT, 256, SM_DYN>>>(F_SPLIT);

    // k_final additionally needs k_wt; accumulates directly into out[0]
    cudaStreamWaitEvent(0, ev_w, 0);
    k_final<<<P_, 256>>>((float*)d_out);
}

// round 15
// speedup vs baseline: 1.0552x; 1.0552x over previous
#include <cuda_runtime.h>
#include <cuda_bf16.h>
#include <cstdint>

#define B_ 512
#define D_ 256
#define P_ 196
#define N2 1024   // 2*B
#define P0 6      // positions beyond this: softmax chain converged to uniform

// exp(dot / T) with T=0.5 -> exp2(dot * 2*log2(e))
#define EXP_SCALE 2.8853900817779268f
#define LOG2E     1.4426950408889634f
#define LN2F      0.6931471805599453f
#define E_SQ      7.3890560989306495f   // e^2 = exp(u.u / T)

#define NTILE_FULL 36                   // 8x8 upper triangle
#define NTILE_AA   10                   // 4x4 upper triangle
#define GRID_MAIN  (P0 * NTILE_FULL + (P_ - P0) * NTILE_AA)   // 2116

// ---------------- device scratch (no allocations allowed) ----------------
__device__ __nv_bfloat16 g_Zh[(size_t)P_ * N2 * D_];  // [p][row][d] bf16
__device__ float g_S[P_ * N2];      // per-row sums of exp(sim) (atomic accum)
__device__ float g_rn2[P_ * N2];    // per-row |z|^2 (diag correction)
__device__ float g_invA[P_ * B_];   // per-A-row 1/(||softmax||+1e-8)
__device__ float g_wtp[128 * P_];   // attention-sum partials (128 row-groups)
__device__ float g_dsum[P_];        // positive-pair dots (atomic accum, p<P0)

// ---------------- small helpers ----------------
__device__ __forceinline__ float ex2f(float x) {
    float y; asm("ex2.approx.f32 %0, %1;" : "=f"(y) : "f"(x)); return y;
}
__device__ __forceinline__ float lg2f(float x) {
    float y; asm("lg2.approx.f32 %0, %1;" : "=f"(y) : "f"(x)); return y;
}
__device__ __forceinline__ unsigned s2u(const void* p) {
    return (unsigned)__cvta_generic_to_shared(p);
}
__device__ __forceinline__ float warpSum(float v) {
    #pragma unroll
    for (int o = 16; o > 0; o >>= 1) v += __shfl_xor_sync(0xffffffffu, v, o);
    return v;
}
__device__ __forceinline__ float blockSum256(float v, float* sh) {
    int w = threadIdx.x >> 5, l = threadIdx.x & 31;
    v = warpSum(v);
    __syncthreads();
    if (l == 0) sh[w] = v;
    __syncthreads();
    if (w == 0) {
        float x = (l < 8) ? sh[l] : 0.0f;
        x = warpSum(x);
        if (l == 0) sh[0] = x;
    }
    __syncthreads();
    return sh[0];
}

#define CPA16(dst_, src_) \
    asm volatile("cp.async.cg.shared.global [%0], [%1], 16;" :: "r"(dst_), "l"(src_))
#define CPA_COMMIT() asm volatile("cp.async.commit_group;" ::: "memory")
#define CPA_WAITG1() asm volatile("cp.async.wait_group 1;"  ::: "memory")

#define LDSM4(r0_, r1_, r2_, r3_, addr_) \
    asm volatile("ldmatrix.sync.aligned.m8n8.x4.shared.b16 {%0,%1,%2,%3}, [%4];" \
        : "=r"(r0_), "=r"(r1_), "=r"(r2_), "=r"(r3_) : "r"(addr_))

#define MMA16816(c_, a_, b0_, b1_) \
    asm volatile("mma.sync.aligned.m16n8k16.row.col.f32.bf16.bf16.f32 " \
        "{%0,%1,%2,%3}, {%4,%5,%6,%7}, {%8,%9}, {%0,%1,%2,%3};" \
        : "+f"((c_)[0]), "+f"((c_)[1]), "+f"((c_)[2]), "+f"((c_)[3]) \
        : "r"((a_)[0]), "r"((a_)[1]), "r"((a_)[2]), "r"((a_)[3]), "r"(b0_), "r"(b1_))

// ---------------- zero accumulators (+ output) ----------------
__global__ __launch_bounds__(1024) void k_zero(float* out, int n) {
    int b = blockIdx.x, t = threadIdx.x;
    g_S[b * 1024 + t] = 0.0f;
    if (t == 0 && b < P_) g_dsum[b] = 0.0f;
    if (b == 0) for (int i = t; i < n; i += 1024) out[i] = 0.0f;
}

// ---------------- stage 1: global-feature softmax chain (p < P0 only) -------
__global__ __launch_bounds__(32) void k_buildG(const float* __restrict__ gf) {
    int b = blockIdx.x;
    int lane = threadIdx.x;
    float v[8];
    #pragma unroll
    for (int j = 0; j < 8; j++) v[j] = gf[b * D_ + j * 32 + lane];
    for (int p = 0; p < P0; p++) {
        float e[8], s = 0.0f, s2 = 0.0f;
        #pragma unroll
        for (int j = 0; j < 8; j++) {
            e[j] = ex2f(v[j] * LOG2E);
            s  += e[j];
            s2 += e[j] * e[j];
        }
        #pragma unroll
        for (int o = 16; o > 0; o >>= 1) {
            s  += __shfl_xor_sync(~0u, s,  o);
            s2 += __shfl_xor_sync(~0u, s2, o);
        }
        float inv_s = 1.0f / s;
        float q = s2 * inv_s * inv_s;
        float inv = 1.0f / (sqrtf(q) + 1e-8f);
        float sc = inv_s * inv;
        #pragma unroll
        for (int j = 0; j < 8; j++) {
            g_Zh[((size_t)p * N2 + B_ + b) * D_ + j * 32 + lane] =
                __float2bfloat16(e[j] * sc);
            v[j] = e[j] * inv_s;
        }
        if (lane == 0) g_rn2[p * N2 + B_ + b] = q * inv * inv;
    }
}

// ---------------- stage 2: local-feature softmax (32 p per block) ------------
// fp32 tile transposed [d][p], pitch 36 words; bf16 staging pitch 132 words.
#define TP 36
__global__ __launch_bounds__(256) void k_buildA(const float* __restrict__ outp) {
    __shared__ float tile[D_ * TP];          // 36864 B
    int pg = blockIdx.x, b = blockIdx.y;
    int tid = threadIdx.x;
    // vector load phase: 8 x (LDG.128 -> STS.128)
    #pragma unroll
    for (int i = 0; i < 8; i++) {
        int idx = tid + (i << 8);            // 0..2047
        int d = idx >> 3, p4 = idx & 7;
        int pbase = pg * 32 + p4 * 4;
        if (pbase > P_ - 4) pbase = P_ - 4;  // clamp: dup columns land in discarded p>=196 slots
        float4 v = *(const float4*)(outp + ((size_t)b * D_ + d) * P_ + pbase);
        *(float4*)(tile + d * TP + p4 * 4) = v;
    }
    __syncthreads();
    int dg = tid & 7, pl = tid >> 3;
    int p  = pg * 32 + pl;
    float x[32];
    #pragma unroll
    for (int j = 0; j < 32; j++) x[j] = tile[(dg + 8 * j) * TP + pl];
    float e[32], s = 0.0f, s2 = 0.0f;
    #pragma unroll
    for (int j = 0; j < 32; j++) {
        e[j] = ex2f(x[j] * LOG2E);
        s += e[j]; s2 += e[j] * e[j];
    }
    s  += __shfl_xor_sync(~0u, s, 1);  s  += __shfl_xor_sync(~0u, s, 2);  s  += __shfl_xor_sync(~0u, s, 4);
    s2 += __shfl_xor_sync(~0u, s2, 1); s2 += __shfl_xor_sync(~0u, s2, 2); s2 += __shfl_xor_sync(~0u, s2, 4);
    float inv_s = 1.0f / s;
    float q = s2 * inv_s * inv_s;
    float inv = 1.0f / (sqrtf(q) + 1e-8f);
    float sc = inv_s * inv;
    if (dg == 0 && p < P_) {
        g_rn2[p * N2 + b] = q * inv * inv;
        g_invA[p * B_ + b] = inv;
    }
    __syncthreads();
    __nv_bfloat16* stg = (__nv_bfloat16*)tile;   // reuse: 32 rows x 264 bf16 (132 words)
    #pragma unroll
    for (int j = 0; j < 32; j++) stg[pl * 264 + dg + 8 * j] = __float2bfloat16(e[j] * sc);
    __syncthreads();
    const uint4* stg4 = (const uint4*)tile;      // row pitch 132 words = 33 uint4
    uint4* dst = (uint4*)g_Zh;                   // row = 128 u32 = 32 uint4
    #pragma unroll
    for (int i = 0; i < 4; i++) {
        int idx = tid + (i << 8);                // 0..1023
        int pl2 = idx >> 5, dw = idx & 31;
        int pp = pg * 32 + pl2;
        if (pp < P_) dst[((size_t)pp * N2 + b) * 32 + dw] = stg4[pl2 * 33 + dw];
    }
}

// ---------------- attention weights: 128 coalesced partial blocks ------------
__global__ __launch_bounds__(256) void k_wt(const float* __restrict__ att) {
    int t = threadIdx.x;
    int g = blockIdx.x;               // 128 blocks, 32 rows each
    if (t >= P_) return;
    const float* base = att + (size_t)(g * 32) * P_ + t;
    float s = 0.0f;
    #pragma unroll 8
    for (int r = 0; r < 32; r++) s += base[(size_t)r * P_];
    g_wtp[g * P_ + t] = s;
}

// ---------------- main: one 128x128 tile pair per CTA, packed grid ----------
#define CH_STRIDE 80                 // 32 bf16 = 64B + 16 pad per row
#define CH_BYTES  (128 * CH_STRIDE)  // one operand chunk: 10240
#define STG_BYTES (2 * CH_BYTES)     // A chunk + B chunk per stage
#define NSTAGE    3
#define SM_DYN    (NSTAGE * STG_BYTES)   // 61440

__global__ __launch_bounds__(256, 2) void k_main_mma() {
    extern __shared__ __align__(1024) char dynsm[];
    __shared__ float redsm[4 * 128];
    __shared__ float colsm[2][128];
    __shared__ float shred[32];

    uint32_t sm_u = s2u(dynsm);

    int tid  = threadIdx.x;
    int wid  = tid >> 5;
    int lane = tid & 31;
    int gq   = lane >> 2;
    int t4   = lane & 3;

    // flat packed decode: P0 p's x 36 tiles, then (P_-P0) p's x 10 tiles
    int f = blockIdx.x;
    int p, ti, width;
    if (f < P0 * NTILE_FULL) {
        p = f / NTILE_FULL; ti = f - p * NTILE_FULL; width = 8;
    } else {
        int f2 = f - P0 * NTILE_FULL;
        int pr = f2 / NTILE_AA;
        p = P0 + pr; ti = f2 - pr * NTILE_AA; width = 4;
    }
    int rt = 0;
    while (ti >= width - rt) { ti -= width - rt; rt++; }
    int ct = rt + ti;
    int r0 = rt << 7, c0 = ct << 7;
    bool diag = (rt == ct);

    int mwarp = wid & 1, nwarp = wid >> 1;
    int mbase = mwarp << 6;
    int nwbase = nwarp << 5;

    const __nv_bfloat16* Zh = g_Zh + (size_t)p * (N2 * D_);

    int q    = lane >> 3;
    int arow = ((q & 1) << 3) + (lane & 7);
    uint32_t aoff = (uint32_t)(arow * CH_STRIDE + ((q >> 1) << 4));
    uint32_t boff = (uint32_t)(((((q >> 1) << 3) + (lane & 7)) * CH_STRIDE) + ((q & 1) << 4));

    // per-thread cp.async coords (2 granules per operand per chunk)
    int n_0 = tid >> 2,         g4_0 = tid & 3;
    int n_1 = (tid + 256) >> 2, g4_1 = (tid + 256) & 3;

    // ---- prologue: stages 0,1 ----
    #pragma unroll
    for (int st = 0; st < 2; st++) {
        uint32_t sbase = sm_u + st * STG_BYTES;
        int kc = st;
        CPA16(sbase + (uint32_t)(n_0 * CH_STRIDE + g4_0 * 16),
              Zh + (size_t)(r0 + n_0) * D_ + kc * 32 + g4_0 * 8);
        CPA16(sbase + (uint32_t)(n_1 * CH_STRIDE + g4_1 * 16),
              Zh + (size_t)(r0 + n_1) * D_ + kc * 32 + g4_1 * 8);
        if (!diag) {
            CPA16(sbase + (uint32_t)(CH_BYTES + n_0 * CH_STRIDE + g4_0 * 16),
                  Zh + (size_t)(c0 + n_0) * D_ + kc * 32 + g4_0 * 8);
            CPA16(sbase + (uint32_t)(CH_BYTES + n_1 * CH_STRIDE + g4_1 * 16),
                  Zh + (size_t)(c0 + n_1) * D_ + kc * 32 + g4_1 * 8);
        }
        CPA_COMMIT();
    }

    float acc[4][4][4];
    #pragma unroll
    for (int mb = 0; mb < 4; mb++)
        #pragma unroll
        for (int nb = 0; nb < 4; nb++)
            #pragma unroll
            for (int r = 0; r < 4; r++) acc[mb][nb][r] = 0.0f;

    uint32_t bsel = diag ? 0u : (uint32_t)CH_BYTES;   // diag reuses A chunk as B

    int stage = 0;
    #pragma unroll 1
    for (int kc = 0; kc < 8; kc++) {
        CPA_WAITG1();
        __syncthreads();
        // prefetch kc+2
        int kn = kc + 2;
        if (kn < 8) {
            int sn = kn % NSTAGE;
            uint32_t sbase = sm_u + sn * STG_BYTES;
            CPA16(sbase + (uint32_t)(n_0 * CH_STRIDE + g4_0 * 16),
                  Zh + (size_t)(r0 + n_0) * D_ + kn * 32 + g4_0 * 8);
            CPA16(sbase + (uint32_t)(n_1 * CH_STRIDE + g4_1 * 16),
                  Zh + (size_t)(r0 + n_1) * D_ + kn * 32 + g4_1 * 8);
            if (!diag) {
                CPA16(sbase + (uint32_t)(CH_BYTES + n_0 * CH_STRIDE + g4_0 * 16),
                      Zh + (size_t)(c0 + n_0) * D_ + kn * 32 + g4_0 * 8);
                CPA16(sbase + (uint32_t)(CH_BYTES + n_1 * CH_STRIDE + g4_1 * 16),
                      Zh + (size_t)(c0 + n_1) * D_ + kn * 32 + g4_1 * 8);
            }
        }
        CPA_COMMIT();

        uint32_t abase = sm_u + (uint32_t)(stage * STG_BYTES);
        uint32_t bbase = abase + bsel;
        #pragma unroll
        for (int kh = 0; kh < 2; kh++) {
            uint32_t a[4][4];
            #pragma unroll
            for (int mb = 0; mb < 4; mb++) {
                uint32_t addr = abase + (uint32_t)((mbase + (mb << 4)) * CH_STRIDE + (kh << 5)) + aoff;
                LDSM4(a[mb][0], a[mb][1], a[mb][2], a[mb][3], addr);
            }
            uint32_t bf[2][4];
            #pragma unroll
            for (int n2 = 0; n2 < 2; n2++) {
                uint32_t addr = bbase + (uint32_t)((nwbase + (n2 << 4)) * CH_STRIDE + (kh << 5)) + boff;
                LDSM4(bf[n2][0], bf[n2][1], bf[n2][2], bf[n2][3], addr);
            }
            #pragma unroll
            for (int mb = 0; mb < 4; mb++) {
                MMA16816(acc[mb][0], a[mb], bf[0][0], bf[0][1]);
                MMA16816(acc[mb][1], a[mb], bf[0][2], bf[0][3]);
                MMA16816(acc[mb][2], a[mb], bf[1][0], bf[1][1]);
                MMA16816(acc[mb][3], a[mb], bf[1][2], bf[1][3]);
            }
        }
        stage++; if (stage == NSTAGE) stage = 0;
    }

    // ---- epilogue: exp, rowsums (+ colsums if off-diag), pair dots ----
    bool isdiag4 = (p < P0) && (ct == rt + 4);
    float cs[8];
    #pragma unroll
    for (int i = 0; i < 8; i++) cs[i] = 0.0f;
    float dpart = 0.0f;
    float rs_reg[8];
    #pragma unroll
    for (int mb = 0; mb < 4; mb++) {
        int row0 = mbase + (mb << 4) + gq;
        float rs0 = 0.0f, rs1 = 0.0f;
        #pragma unroll
        for (int nb = 0; nb < 4; nb++) {
            int col = nwbase + (nb << 3) + (t4 << 1);
            float* c = acc[mb][nb];
            float e0 = ex2f(c[0] * EXP_SCALE);
            float e1 = ex2f(c[1] * EXP_SCALE);
            float e2 = ex2f(c[2] * EXP_SCALE);
            float e3 = ex2f(c[3] * EXP_SCALE);
            rs0 += e0 + e1;
            rs1 += e2 + e3;
            cs[nb * 2 + 0] += e0 + e2;
            cs[nb * 2 + 1] += e1 + e3;
            if (isdiag4) {
                if (col == row0)          dpart += c[0];
                else if (col + 1 == row0) dpart += c[1];
                if (col == row0 + 8)          dpart += c[2];
                else if (col + 1 == row0 + 8) dpart += c[3];
            }
        }
        rs_reg[mb * 2 + 0] = rs0;
        rs_reg[mb * 2 + 1] = rs1;
    }

    // rowsums: reduce over t4, combine across nwarp via smem, one atomic per row
    #pragma unroll
    for (int i = 0; i < 8; i++) {
        rs_reg[i] += __shfl_xor_sync(~0u, rs_reg[i], 1);
        rs_reg[i] += __shfl_xor_sync(~0u, rs_reg[i], 2);
    }
    if (t4 == 0) {
        #pragma unroll
        for (int mb = 0; mb < 4; mb++) {
            int row0 = mbase + (mb << 4) + gq;
            redsm[nwarp * 128 + row0]     = rs_reg[mb * 2 + 0];
            redsm[nwarp * 128 + row0 + 8] = rs_reg[mb * 2 + 1];
        }
    }
    // colsums: reduce across gq lanes, combine across mwarp via smem
    if (!diag) {
        #pragma unroll
        for (int i = 0; i < 8; i++) {
            cs[i] += __shfl_xor_sync(~0u, cs[i], 4);
            cs[i] += __shfl_xor_sync(~0u, cs[i], 8);
            cs[i] += __shfl_xor_sync(~0u, cs[i], 16);
        }
        if (lane < 4) {
            #pragma unroll
            for (int i = 0; i < 8; i++)
                colsm[mwarp][nwbase + ((i >> 1) << 3) + lane * 2 + (i & 1)] = cs[i];
        }
    }
    __syncthreads();
    if (tid < 128) {
        float rsum = redsm[tid] + redsm[128 + tid] + redsm[256 + tid] + redsm[384 + tid];
        atomicAdd(&g_S[p * N2 + r0 + tid], rsum);
        if (!diag)
            atomicAdd(&g_S[p * N2 + c0 + tid], colsm[0][tid] + colsm[1][tid]);
    }
    if (isdiag4) {
        float dp = blockSum256(dpart, shred);
        if (tid == 0) atomicAdd(&g_dsum[p], dp);
    }
}

// ---------------- per-position loss -> atomic into out[0] ----------------
__global__ __launch_bounds__(256) void k_final(float* out) {
    int p = blockIdx.x;
    __shared__ float sh[32];
    __shared__ float sh_wt;
    // parallel attention-weight partial reduction (128 partials)
    float wt_part = (threadIdx.x < 128) ? g_wtp[threadIdx.x * P_ + p] : 0.0f;
    float wt = blockSum256(wt_part, sh);
    if (threadIdx.x == 0) sh_wt = wt;

    if (p < P0) {
        float acc = 0.0f;
        for (int r = threadIdx.x; r < N2; r += 256) {
            float self = ex2f(g_rn2[p * N2 + r] * EXP_SCALE);
            acc += lg2f(g_S[p * N2 + r] - self);
        }
        acc = blockSum256(acc, sh) * LN2F;
        if (threadIdx.x == 0) {
            atomicAdd(out, (acc - 4.0f * g_dsum[p]) * sh_wt *
                           (1.0f / ((float)N2 * (float)B_ * (float)P_)));
        }
    } else {
        // converged regime: G rows all equal u (entries 1/16).
        float accL = 0.0f, accT = 0.0f, accD = 0.0f;
        for (int r = threadIdx.x; r < B_; r += 256) {
            float Saa  = g_S[p * N2 + r];                   // AA exp-rowsum (incl. bf16 self)
            float inv  = g_invA[p * B_ + r];
            float dAu  = inv * 0.0625f;                     // dot(A_r, u)
            float E    = ex2f(dAu * EXP_SCALE);             // exp(2*dAu)
            float self = ex2f(g_rn2[p * N2 + r] * EXP_SCALE);
            accL += lg2f(Saa + 512.0f * E - self);
            accT += E;
            accD += dAu;
        }
        accL = blockSum256(accL, sh);
        accT = blockSum256(accT, sh);
        accD = blockSum256(accD, sh);
        if (threadIdx.x == 0) {
            // G rows: S = T_A + 512*e^2, self = e^2 -> 512 identical log terms
            float logAll = (accL + 512.0f * lg2f(accT + 511.0f * E_SQ)) * LN2F;
            atomicAdd(out, (logAll - 4.0f * accD) * sh_wt *
                           (1.0f / ((float)N2 * (float)B_ * (float)P_)));
        }
    }
}

// ---------------- launch ----------------
extern "C" void kernel_launch(void* const* d_in, const int* in_sizes, int n_in,
                              void* d_out, int out_size) {
    const float* gf = nullptr; const float* att = nullptr; const float* outp = nullptr;
    for (int i = 0; i < n_in; i++) {
        if (in_sizes[i] == B_ * D_)            gf   = (const float*)d_in[i];
        else if (in_sizes[i] == B_ * 8 * P_)   att  = (const float*)d_in[i];
        else if (in_sizes[i] == B_ * D_ * P_)  outp = (const float*)d_in[i];
    }
    if (!gf)   gf   = (const float*)d_in[0];
    if (!att)  att  = (const float*)d_in[1];
    if (!outp) outp = (const float*)d_in[2];

    cudaFuncSetAttribute(k_main_mma, cudaFuncAttributeMaxDynamicSharedMemorySize, SM_DYN);

    // one-time resources (no device memory involved); work per call is identical
    static cudaStream_t s_g = nullptr, s_z = nullptr;
    static cudaEvent_t ev_root = nullptr, ev_g = nullptr, ev_z = nullptr, ev_w = nullptr;
    if (s_g == nullptr) {
        cudaStreamCreateWithFlags(&s_g, cudaStreamNonBlocking);
        cudaStreamCreateWithFlags(&s_z, cudaStreamNonBlocking);
        cudaEventCreateWithFlags(&ev_root, cudaEventDisableTiming);
        cudaEventCreateWithFlags(&ev_g,    cudaEventDisableTiming);
        cudaEventCreateWithFlags(&ev_z,    cudaEventDisableTiming);
        cudaEventCreateWithFlags(&ev_w,    cudaEventDisableTiming);
    }

    // fork from the (captured) default stream
    cudaEventRecord(ev_root, 0);
    cudaStreamWaitEvent(s_g, ev_root, 0);
    cudaStreamWaitEvent(s_z, ev_root, 0);

    k_buildG<<<B_, 32, 0, s_g>>>(gf);
    cudaEventRecord(ev_g, s_g);

    k_zero<<<P_, 1024, 0, s_z>>>((float*)d_out, out_size);
    cudaEventRecord(ev_z, s_z);
    k_wt<<<128, 256, 0, s_z>>>(att);
    cudaEventRecord(ev_w, s_z);

    k_buildA<<<dim3(7, B_), 256>>>(outp);       // default stream (bulk work)

    // join: k_main needs buildG + zero (+ buildA, same stream)
    cudaStreamWaitEvent(0, ev_g, 0);
    cudaStreamWaitEvent(0, ev_z, 0);
    k_main_mma<<<GRID_MAIN, 256, SM_DYN>>>();

    // k_final additionally needs k_wt; accumulates directly into out[0]
    cudaStreamWaitEvent(0, ev_w, 0);
    k_final<<<P_, 256>>>((float*)d_out);
}